// round 1
// baseline (speedup 1.0000x reference)
#include <cuda_runtime.h>
#include <math.h>

// Problem constants
#define PB 4
#define PS 1024
#define PD 2048
#define PH 16
#define PG 2
#define PHD 128
#define PBS (PB * PS)          // 4096 rows
#define KVW (PG * PHD)         // 256

// ---------------- scratch (device globals; no allocation allowed) ----------
__device__ float g_Q[PBS * PD];        // 32 MB
__device__ float g_K[PBS * KVW];       // 4 MB
__device__ float g_V[PBS * KVW];       // 4 MB
__device__ float g_AO[PBS * PD];       // 32 MB

// ---------------- SGEMM: C[M,N] = A[M,K] @ W[K,N] + bias[N] ----------------
// BM=128, BN=128, BK=8, 256 threads, 8x8 microtile.
#define BM 128
#define BN 128
#define BK 8

__global__ __launch_bounds__(256, 2)
void sgemm_bias(const float* __restrict__ A, const float* __restrict__ W,
                const float* __restrict__ bias, float* __restrict__ C,
                int M, int N, int K) {
    __shared__ float As[BK][BM];   // transposed A tile
    __shared__ float Bs[BK][BN];

    const int tid = threadIdx.x;
    const int tx = tid & 15;       // 0..15 (N direction)
    const int ty = tid >> 4;       // 0..15 (M direction)
    const int bx = blockIdx.x;     // N tile
    const int by = blockIdx.y;     // M tile

    // A tile loads: 128x8 floats = 256 float4; thread -> (row=tid>>1, quad=(tid&1)*4)
    const int a_row  = tid >> 1;
    const int a_col4 = (tid & 1) * 4;
    // B tile loads: 8x128 floats = 256 float4; thread -> (row=tid>>5, col4=(tid&31)*4)
    const int b_row  = tid >> 5;
    const int b_col4 = (tid & 31) * 4;

    const float* Ap = A + (size_t)(by * BM + a_row) * K;
    const float* Wp = W + (size_t)bx * BN;

    float acc[8][8];
#pragma unroll
    for (int i = 0; i < 8; i++)
#pragma unroll
        for (int j = 0; j < 8; j++) acc[i][j] = 0.f;

    for (int k0 = 0; k0 < K; k0 += BK) {
        float4 av = *(const float4*)(Ap + k0 + a_col4);
        As[a_col4 + 0][a_row] = av.x;
        As[a_col4 + 1][a_row] = av.y;
        As[a_col4 + 2][a_row] = av.z;
        As[a_col4 + 3][a_row] = av.w;
        float4 bv = *(const float4*)(Wp + (size_t)(k0 + b_row) * N + b_col4);
        *(float4*)&Bs[b_row][b_col4] = bv;
        __syncthreads();

#pragma unroll
        for (int k = 0; k < BK; k++) {
            float ra[8], rb[8];
            *(float4*)&ra[0] = *(const float4*)&As[k][ty * 8 + 0];
            *(float4*)&ra[4] = *(const float4*)&As[k][ty * 8 + 4];
            *(float4*)&rb[0] = *(const float4*)&Bs[k][tx * 8 + 0];
            *(float4*)&rb[4] = *(const float4*)&Bs[k][tx * 8 + 4];
#pragma unroll
            for (int i = 0; i < 8; i++)
#pragma unroll
                for (int j = 0; j < 8; j++) acc[i][j] += ra[i] * rb[j];
        }
        __syncthreads();
    }

    // epilogue with bias
    const int col = bx * BN + tx * 8;
    float bsv[8];
    *(float4*)&bsv[0] = *(const float4*)(bias + col);
    *(float4*)&bsv[4] = *(const float4*)(bias + col + 4);
#pragma unroll
    for (int i = 0; i < 8; i++) {
        const int row = by * BM + ty * 8 + i;
        float4 o0, o1;
        o0.x = acc[i][0] + bsv[0]; o0.y = acc[i][1] + bsv[1];
        o0.z = acc[i][2] + bsv[2]; o0.w = acc[i][3] + bsv[3];
        o1.x = acc[i][4] + bsv[4]; o1.y = acc[i][5] + bsv[5];
        o1.z = acc[i][6] + bsv[6]; o1.w = acc[i][7] + bsv[7];
        *(float4*)(C + (size_t)row * N + col)     = o0;
        *(float4*)(C + (size_t)row * N + col + 4) = o1;
    }
}

// ---------------- RoPE (in place) ------------------------------------------
// data layout: [BS, nheads*128]; pair (i, i+64) per head, angle = s * 10000^(-i/64)
__global__ void rope_kernel(float* __restrict__ data, int nheads, float outscale) {
    int idx = blockIdx.x * blockDim.x + threadIdx.x;   // over BS*nheads*64
    int total = PBS * nheads * 64;
    if (idx >= total) return;
    int i   = idx & 63;
    int t   = idx >> 6;
    int hh  = t % nheads;
    int row = t / nheads;
    int s   = row & (PS - 1);

    float inv = powf(10000.f, -(float)i / 64.f);
    float ang = (float)s * inv;
    float sn, cs;
    sincosf(ang, &sn, &cs);

    float* p = data + (size_t)row * (nheads * PHD) + hh * PHD;
    float x1 = p[i];
    float x2 = p[i + 64];
    p[i]      = (x1 * cs - x2 * sn) * outscale;
    p[i + 64] = (x2 * cs + x1 * sn) * outscale;
}

// ---------------- Flash attention ------------------------------------------
// Br=64 query rows/block, Bc=32 key cols/tile, HD=128. 256 threads as 16x16.
// Each thread: 4 q-rows (ty), 2 score cols / 8 out cols (tx).
#define FBR 64
#define FBC 32
#define KS_STR 132
#define PS_STR 36
#define FLASH_SMEM ((FBR*PHD + 2*FBC*KS_STR + FBR*PS_STR) * sizeof(float))

__global__ __launch_bounds__(256, 2)
void flash_kernel(const float* __restrict__ Q, const float* __restrict__ K,
                  const float* __restrict__ V, float* __restrict__ O) {
    extern __shared__ float sm[];
    float* Qs = sm;                       // 64 x 128
    float* Ks = Qs + FBR * PHD;           // 32 x 132
    float* Vs = Ks + FBC * KS_STR;        // 32 x 132
    float* Ps = Vs + FBC * KS_STR;        // 64 x 36

    const int tid = threadIdx.x;
    const int tx = tid & 15;
    const int ty = tid >> 4;
    const int qtile = blockIdx.x;         // 0..15
    const int bh = blockIdx.y;            // 0..63
    const int b = bh / PH, h = bh % PH;
    const int g = h / (PH / PG);

    const float* Qb = Q + ((size_t)(b * PS + qtile * FBR)) * PD + h * PHD;
    const float* Kb = K + ((size_t)(b * PS)) * KVW + g * PHD;
    const float* Vb = V + ((size_t)(b * PS)) * KVW + g * PHD;

    // load Q tile (2048 float4)
    for (int i = tid; i < FBR * (PHD / 4); i += 256) {
        int row = i >> 5, c4 = i & 31;
        *(float4*)&Qs[row * PHD + c4 * 4] = *(const float4*)(Qb + (size_t)row * PD + c4 * 4);
    }

    float m[4], l[4], acc[4][8];
#pragma unroll
    for (int i = 0; i < 4; i++) {
        m[i] = -INFINITY; l[i] = 0.f;
#pragma unroll
        for (int j = 0; j < 8; j++) acc[i][j] = 0.f;
    }

    const float sc = 0.08838834764831845f;  // hd^-0.5 (second scaling)

    for (int k0 = 0; k0 < PS; k0 += FBC) {
        // load K,V tiles (1024 float4 each -> 4 per thread each)
        for (int i = tid; i < FBC * (PHD / 4); i += 256) {
            int row = i >> 5, c4 = i & 31;
            *(float4*)&Ks[row * KS_STR + c4 * 4] =
                *(const float4*)(Kb + (size_t)(k0 + row) * KVW + c4 * 4);
            *(float4*)&Vs[row * KS_STR + c4 * 4] =
                *(const float4*)(Vb + (size_t)(k0 + row) * KVW + c4 * 4);
        }
        __syncthreads();

        // scores: 4 rows x 2 cols per thread, dot over 128
        float s[4][2];
#pragma unroll
        for (int i = 0; i < 4; i++) { s[i][0] = 0.f; s[i][1] = 0.f; }
        const float4* Q4 = (const float4*)Qs;
#pragma unroll 8
        for (int d4 = 0; d4 < 32; d4++) {
            float4 kv0 = *(const float4*)&Ks[(tx * 2 + 0) * KS_STR + d4 * 4];
            float4 kv1 = *(const float4*)&Ks[(tx * 2 + 1) * KS_STR + d4 * 4];
#pragma unroll
            for (int i = 0; i < 4; i++) {
                float4 qv = Q4[(ty * 4 + i) * 32 + d4];
                s[i][0] += qv.x * kv0.x + qv.y * kv0.y + qv.z * kv0.z + qv.w * kv0.w;
                s[i][1] += qv.x * kv1.x + qv.y * kv1.y + qv.z * kv1.z + qv.w * kv1.w;
            }
        }

        // online softmax per row (row = 16 lanes of a half-warp)
#pragma unroll
        for (int i = 0; i < 4; i++) {
            float s0 = s[i][0] * sc, s1 = s[i][1] * sc;
            float rm = fmaxf(s0, s1);
#pragma unroll
            for (int off = 8; off >= 1; off >>= 1)
                rm = fmaxf(rm, __shfl_xor_sync(0xffffffffu, rm, off, 16));
            float mnew = fmaxf(m[i], rm);
            float alpha = __expf(m[i] - mnew);
            float p0 = __expf(s0 - mnew);
            float p1 = __expf(s1 - mnew);
            float rs = p0 + p1;
#pragma unroll
            for (int off = 8; off >= 1; off >>= 1)
                rs += __shfl_xor_sync(0xffffffffu, rs, off, 16);
            l[i] = l[i] * alpha + rs;
            m[i] = mnew;
#pragma unroll
            for (int j = 0; j < 8; j++) acc[i][j] *= alpha;
            Ps[(ty * 4 + i) * PS_STR + tx * 2 + 0] = p0;
            Ps[(ty * 4 + i) * PS_STR + tx * 2 + 1] = p1;
        }
        __syncthreads();

        // P @ V accumulate: out cols tx*8..tx*8+7
#pragma unroll 4
        for (int k = 0; k < FBC; k++) {
            float4 v0 = *(const float4*)&Vs[k * KS_STR + tx * 8];
            float4 v1 = *(const float4*)&Vs[k * KS_STR + tx * 8 + 4];
#pragma unroll
            for (int i = 0; i < 4; i++) {
                float p = Ps[(ty * 4 + i) * PS_STR + k];
                acc[i][0] += p * v0.x; acc[i][1] += p * v0.y;
                acc[i][2] += p * v0.z; acc[i][3] += p * v0.w;
                acc[i][4] += p * v1.x; acc[i][5] += p * v1.y;
                acc[i][6] += p * v1.z; acc[i][7] += p * v1.w;
            }
        }
        __syncthreads();
    }

    // normalize + write
#pragma unroll
    for (int i = 0; i < 4; i++) {
        float inv = 1.f / l[i];
        int row = qtile * FBR + ty * 4 + i;
        float* op = O + ((size_t)(b * PS + row)) * PD + h * PHD + tx * 8;
        float4 o0, o1;
        o0.x = acc[i][0] * inv; o0.y = acc[i][1] * inv;
        o0.z = acc[i][2] * inv; o0.w = acc[i][3] * inv;
        o1.x = acc[i][4] * inv; o1.y = acc[i][5] * inv;
        o1.z = acc[i][6] * inv; o1.w = acc[i][7] * inv;
        *(float4*)op = o0;
        *(float4*)(op + 4) = o1;
    }
}

// ---------------- launch ----------------------------------------------------
extern "C" void kernel_launch(void* const* d_in, const int* in_sizes, int n_in,
                              void* d_out, int out_size) {
    const float* x  = (const float*)d_in[0];
    const float* wq = (const float*)d_in[1];
    const float* bq = (const float*)d_in[2];
    const float* wk = (const float*)d_in[3];
    const float* bk = (const float*)d_in[4];
    const float* wv = (const float*)d_in[5];
    const float* bv = (const float*)d_in[6];
    const float* wo = (const float*)d_in[7];
    const float* bo = (const float*)d_in[8];
    float* out = (float*)d_out;

    float *pQ, *pK, *pV, *pAO;
    cudaGetSymbolAddress((void**)&pQ,  g_Q);
    cudaGetSymbolAddress((void**)&pK,  g_K);
    cudaGetSymbolAddress((void**)&pV,  g_V);
    cudaGetSymbolAddress((void**)&pAO, g_AO);

    cudaFuncSetAttribute(flash_kernel, cudaFuncAttributeMaxDynamicSharedMemorySize,
                         (int)FLASH_SMEM);

    // QKV projections
    sgemm_bias<<<dim3(PD / BN, PBS / BM), 256>>>(x, wq, bq, pQ, PBS, PD, PD);
    sgemm_bias<<<dim3(KVW / BN, PBS / BM), 256>>>(x, wk, bk, pK, PBS, KVW, PD);
    sgemm_bias<<<dim3(KVW / BN, PBS / BM), 256>>>(x, wv, bv, pV, PBS, KVW, PD);

    // RoPE: Q gets the extra hd^-0.5 pre-scale; K plain.
    {
        int nq = PBS * PH * 64;
        rope_kernel<<<(nq + 255) / 256, 256>>>(pQ, PH, 0.08838834764831845f);
        int nk = PBS * PG * 64;
        rope_kernel<<<(nk + 255) / 256, 256>>>(pK, PG, 1.0f);
    }

    // attention
    flash_kernel<<<dim3(PS / FBR, PB * PH), 256, FLASH_SMEM>>>(pQ, pK, pV, pAO);

    // output projection
    sgemm_bias<<<dim3(PD / BN, PBS / BM), 256>>>(pAO, wo, bo, out, PBS, PD, PD);
}

// round 2
// speedup vs baseline: 1.6894x; 1.6894x over previous
#include <cuda_runtime.h>
#include <math.h>
#include <stdint.h>

// Problem constants
#define PB 4
#define PS 1024
#define PD 2048
#define PH 16
#define PG 2
#define PHD 128
#define PBS (PB * PS)          // 4096 rows
#define KVW (PG * PHD)         // 256

// ---------------- scratch (device globals; no allocation allowed) ----------
__device__ float g_Q[PBS * PD];        // 32 MB
__device__ float g_K[PBS * KVW];       // 4 MB
__device__ float g_V[PBS * KVW];       // 4 MB
__device__ float g_AO[PBS * PD];       // 32 MB

// ---------------- tf32 helpers ---------------------------------------------
__device__ __forceinline__ uint32_t f2tf(float x) {
    uint32_t r;
    asm("cvt.rna.tf32.f32 %0, %1;" : "=r"(r) : "f"(x));
    return r;
}

__device__ __forceinline__ void mma_tf32(float* d, const uint32_t* a, const uint32_t* b) {
    asm volatile(
        "mma.sync.aligned.m16n8k8.row.col.f32.tf32.tf32.f32 "
        "{%0,%1,%2,%3}, {%4,%5,%6,%7}, {%8,%9}, {%0,%1,%2,%3};\n"
        : "+f"(d[0]), "+f"(d[1]), "+f"(d[2]), "+f"(d[3])
        : "r"(a[0]), "r"(a[1]), "r"(a[2]), "r"(a[3]), "r"(b[0]), "r"(b[1]));
}

// ---------------- Tensor-core GEMM: C = A[M,K] @ W[K,N] + bias -------------
// BM=128, BN=128, BK=16, 256 threads (8 warps, warp grid 2m x 4n, 64x32/warp)
#define TBM 128
#define TBN 128
#define TBK 16
#define TSTR 136   // smem row stride (mod 32 == 8 -> conflict-free frag loads)

__global__ __launch_bounds__(256, 2)
void tgemm_bias(const float* __restrict__ A, const float* __restrict__ W,
                const float* __restrict__ bias, float* __restrict__ C,
                int M, int N, int K) {
    __shared__ uint32_t As[TBK][TSTR];   // [k][m] (transposed)
    __shared__ uint32_t Bs[TBK][TSTR];   // [k][n]

    const int tid  = threadIdx.x;
    const int lane = tid & 31;
    const int warp = tid >> 5;
    const int wm = (warp & 1) * 64;      // warp m offset
    const int wn = (warp >> 1) * 32;     // warp n offset
    const int bx = blockIdx.x;
    const int by = blockIdx.y;

    // global load mapping
    const int a_row = tid >> 2;          // 0..63 (and +64)
    const int a_c4  = tid & 3;           // k quad
    const int b_row = tid >> 5;          // 0..7 (and +8)
    const int b_c4  = tid & 31;          // n quad

    const float* Ap = A + (size_t)(by * TBM + a_row) * K + a_c4 * 4;
    const float* Bp = W + (size_t)b_row * N + bx * TBN + b_c4 * 4;

    float acc[4][4][4];
#pragma unroll
    for (int i = 0; i < 4; i++)
#pragma unroll
        for (int j = 0; j < 4; j++) {
            acc[i][j][0] = 0.f; acc[i][j][1] = 0.f;
            acc[i][j][2] = 0.f; acc[i][j][3] = 0.f;
        }

    // prefetch first tile
    float4 ar0 = *(const float4*)(Ap);
    float4 ar1 = *(const float4*)(Ap + (size_t)64 * K);
    float4 br0 = *(const float4*)(Bp);
    float4 br1 = *(const float4*)(Bp + (size_t)8 * N);

    for (int k0 = 0; k0 < K; k0 += TBK) {
        // stage to smem (with RN tf32 conversion)
        As[a_c4 * 4 + 0][a_row] = f2tf(ar0.x);
        As[a_c4 * 4 + 1][a_row] = f2tf(ar0.y);
        As[a_c4 * 4 + 2][a_row] = f2tf(ar0.z);
        As[a_c4 * 4 + 3][a_row] = f2tf(ar0.w);
        As[a_c4 * 4 + 0][a_row + 64] = f2tf(ar1.x);
        As[a_c4 * 4 + 1][a_row + 64] = f2tf(ar1.y);
        As[a_c4 * 4 + 2][a_row + 64] = f2tf(ar1.z);
        As[a_c4 * 4 + 3][a_row + 64] = f2tf(ar1.w);
        *(uint4*)&Bs[b_row][b_c4 * 4] =
            make_uint4(f2tf(br0.x), f2tf(br0.y), f2tf(br0.z), f2tf(br0.w));
        *(uint4*)&Bs[b_row + 8][b_c4 * 4] =
            make_uint4(f2tf(br1.x), f2tf(br1.y), f2tf(br1.z), f2tf(br1.w));
        __syncthreads();

        // prefetch next tile (overlaps with compute below)
        if (k0 + TBK < K) {
            ar0 = *(const float4*)(Ap + k0 + TBK);
            ar1 = *(const float4*)(Ap + k0 + TBK + (size_t)64 * K);
            br0 = *(const float4*)(Bp + (size_t)(k0 + TBK) * N);
            br1 = *(const float4*)(Bp + (size_t)(k0 + TBK + 8) * N);
        }

        // compute: two k-chunks of 8
#pragma unroll
        for (int kk = 0; kk < TBK; kk += 8) {
            const int kq = kk + (lane & 3);
            const int gm = lane >> 2;
            uint32_t af[4][4];
#pragma unroll
            for (int mt = 0; mt < 4; mt++) {
                const int m0 = wm + mt * 16 + gm;
                af[mt][0] = As[kq][m0];
                af[mt][1] = As[kq][m0 + 8];
                af[mt][2] = As[kq + 4][m0];
                af[mt][3] = As[kq + 4][m0 + 8];
            }
            uint32_t bf[4][2];
#pragma unroll
            for (int nt = 0; nt < 4; nt++) {
                const int n0 = wn + nt * 8 + gm;
                bf[nt][0] = Bs[kq][n0];
                bf[nt][1] = Bs[kq + 4][n0];
            }
#pragma unroll
            for (int mt = 0; mt < 4; mt++)
#pragma unroll
                for (int nt = 0; nt < 4; nt++)
                    mma_tf32(acc[mt][nt], af[mt], bf[nt]);
        }
        __syncthreads();
    }

    // epilogue with bias
#pragma unroll
    for (int mt = 0; mt < 4; mt++) {
        const int row0 = by * TBM + wm + mt * 16 + (lane >> 2);
#pragma unroll
        for (int nt = 0; nt < 4; nt++) {
            const int col = bx * TBN + wn + nt * 8 + (lane & 3) * 2;
            const float b0 = bias[col], b1 = bias[col + 1];
            float2 v0, v1;
            v0.x = acc[mt][nt][0] + b0; v0.y = acc[mt][nt][1] + b1;
            v1.x = acc[mt][nt][2] + b0; v1.y = acc[mt][nt][3] + b1;
            *(float2*)(C + (size_t)row0 * N + col)       = v0;
            *(float2*)(C + (size_t)(row0 + 8) * N + col) = v1;
        }
    }
}

// ---------------- RoPE (in place) ------------------------------------------
__global__ void rope_kernel(float* __restrict__ data, int nheads, float outscale) {
    int idx = blockIdx.x * blockDim.x + threadIdx.x;   // over BS*nheads*64
    int total = PBS * nheads * 64;
    if (idx >= total) return;
    int i   = idx & 63;
    int t   = idx >> 6;
    int hh  = t % nheads;
    int row = t / nheads;
    int s   = row & (PS - 1);

    float inv = powf(10000.f, -(float)i / 64.f);
    float ang = (float)s * inv;
    float sn, cs;
    sincosf(ang, &sn, &cs);

    float* p = data + (size_t)row * (nheads * PHD) + hh * PHD;
    float x1 = p[i];
    float x2 = p[i + 64];
    p[i]      = (x1 * cs - x2 * sn) * outscale;
    p[i + 64] = (x2 * cs + x1 * sn) * outscale;
}

// ---------------- Flash attention (fp32 SIMT, unchanged) -------------------
#define FBR 64
#define FBC 32
#define KS_STR 132
#define PS_STR 36
#define FLASH_SMEM ((FBR*PHD + 2*FBC*KS_STR + FBR*PS_STR) * sizeof(float))

__global__ __launch_bounds__(256, 2)
void flash_kernel(const float* __restrict__ Q, const float* __restrict__ K,
                  const float* __restrict__ V, float* __restrict__ O) {
    extern __shared__ float sm[];
    float* Qs = sm;                       // 64 x 128
    float* Ks = Qs + FBR * PHD;           // 32 x 132
    float* Vs = Ks + FBC * KS_STR;        // 32 x 132
    float* Ps = Vs + FBC * KS_STR;        // 64 x 36

    const int tid = threadIdx.x;
    const int tx = tid & 15;
    const int ty = tid >> 4;
    const int qtile = blockIdx.x;         // 0..15
    const int bh = blockIdx.y;            // 0..63
    const int b = bh / PH, h = bh % PH;
    const int g = h / (PH / PG);

    const float* Qb = Q + ((size_t)(b * PS + qtile * FBR)) * PD + h * PHD;
    const float* Kb = K + ((size_t)(b * PS)) * KVW + g * PHD;
    const float* Vb = V + ((size_t)(b * PS)) * KVW + g * PHD;

    for (int i = tid; i < FBR * (PHD / 4); i += 256) {
        int row = i >> 5, c4 = i & 31;
        *(float4*)&Qs[row * PHD + c4 * 4] = *(const float4*)(Qb + (size_t)row * PD + c4 * 4);
    }

    float m[4], l[4], acc[4][8];
#pragma unroll
    for (int i = 0; i < 4; i++) {
        m[i] = -INFINITY; l[i] = 0.f;
#pragma unroll
        for (int j = 0; j < 8; j++) acc[i][j] = 0.f;
    }

    const float sc = 0.08838834764831845f;

    for (int k0 = 0; k0 < PS; k0 += FBC) {
        for (int i = tid; i < FBC * (PHD / 4); i += 256) {
            int row = i >> 5, c4 = i & 31;
            *(float4*)&Ks[row * KS_STR + c4 * 4] =
                *(const float4*)(Kb + (size_t)(k0 + row) * KVW + c4 * 4);
            *(float4*)&Vs[row * KS_STR + c4 * 4] =
                *(const float4*)(Vb + (size_t)(k0 + row) * KVW + c4 * 4);
        }
        __syncthreads();

        float s[4][2];
#pragma unroll
        for (int i = 0; i < 4; i++) { s[i][0] = 0.f; s[i][1] = 0.f; }
        const float4* Q4 = (const float4*)Qs;
#pragma unroll 8
        for (int d4 = 0; d4 < 32; d4++) {
            float4 kv0 = *(const float4*)&Ks[(tx * 2 + 0) * KS_STR + d4 * 4];
            float4 kv1 = *(const float4*)&Ks[(tx * 2 + 1) * KS_STR + d4 * 4];
#pragma unroll
            for (int i = 0; i < 4; i++) {
                float4 qv = Q4[(ty * 4 + i) * 32 + d4];
                s[i][0] += qv.x * kv0.x + qv.y * kv0.y + qv.z * kv0.z + qv.w * kv0.w;
                s[i][1] += qv.x * kv1.x + qv.y * kv1.y + qv.z * kv1.z + qv.w * kv1.w;
            }
        }

#pragma unroll
        for (int i = 0; i < 4; i++) {
            float s0 = s[i][0] * sc, s1 = s[i][1] * sc;
            float rm = fmaxf(s0, s1);
#pragma unroll
            for (int off = 8; off >= 1; off >>= 1)
                rm = fmaxf(rm, __shfl_xor_sync(0xffffffffu, rm, off, 16));
            float mnew = fmaxf(m[i], rm);
            float alpha = __expf(m[i] - mnew);
            float p0 = __expf(s0 - mnew);
            float p1 = __expf(s1 - mnew);
            float rs = p0 + p1;
#pragma unroll
            for (int off = 8; off >= 1; off >>= 1)
                rs += __shfl_xor_sync(0xffffffffu, rs, off, 16);
            l[i] = l[i] * alpha + rs;
            m[i] = mnew;
#pragma unroll
            for (int j = 0; j < 8; j++) acc[i][j] *= alpha;
            Ps[(ty * 4 + i) * PS_STR + tx * 2 + 0] = p0;
            Ps[(ty * 4 + i) * PS_STR + tx * 2 + 1] = p1;
        }
        __syncthreads();

#pragma unroll 4
        for (int k = 0; k < FBC; k++) {
            float4 v0 = *(const float4*)&Vs[k * KS_STR + tx * 8];
            float4 v1 = *(const float4*)&Vs[k * KS_STR + tx * 8 + 4];
#pragma unroll
            for (int i = 0; i < 4; i++) {
                float p = Ps[(ty * 4 + i) * PS_STR + k];
                acc[i][0] += p * v0.x; acc[i][1] += p * v0.y;
                acc[i][2] += p * v0.z; acc[i][3] += p * v0.w;
                acc[i][4] += p * v1.x; acc[i][5] += p * v1.y;
                acc[i][6] += p * v1.z; acc[i][7] += p * v1.w;
            }
        }
        __syncthreads();
    }

#pragma unroll
    for (int i = 0; i < 4; i++) {
        float inv = 1.f / l[i];
        int row = qtile * FBR + ty * 4 + i;
        float* op = O + ((size_t)(b * PS + row)) * PD + h * PHD + tx * 8;
        float4 o0, o1;
        o0.x = acc[i][0] * inv; o0.y = acc[i][1] * inv;
        o0.z = acc[i][2] * inv; o0.w = acc[i][3] * inv;
        o1.x = acc[i][4] * inv; o1.y = acc[i][5] * inv;
        o1.z = acc[i][6] * inv; o1.w = acc[i][7] * inv;
        *(float4*)op = o0;
        *(float4*)(op + 4) = o1;
    }
}

// ---------------- launch ----------------------------------------------------
extern "C" void kernel_launch(void* const* d_in, const int* in_sizes, int n_in,
                              void* d_out, int out_size) {
    const float* x  = (const float*)d_in[0];
    const float* wq = (const float*)d_in[1];
    const float* bq = (const float*)d_in[2];
    const float* wk = (const float*)d_in[3];
    const float* bk = (const float*)d_in[4];
    const float* wv = (const float*)d_in[5];
    const float* bv = (const float*)d_in[6];
    const float* wo = (const float*)d_in[7];
    const float* bo = (const float*)d_in[8];
    float* out = (float*)d_out;

    float *pQ, *pK, *pV, *pAO;
    cudaGetSymbolAddress((void**)&pQ,  g_Q);
    cudaGetSymbolAddress((void**)&pK,  g_K);
    cudaGetSymbolAddress((void**)&pV,  g_V);
    cudaGetSymbolAddress((void**)&pAO, g_AO);

    cudaFuncSetAttribute(flash_kernel, cudaFuncAttributeMaxDynamicSharedMemorySize,
                         (int)FLASH_SMEM);

    // QKV projections (tf32 tensor cores)
    tgemm_bias<<<dim3(PD / TBN, PBS / TBM), 256>>>(x, wq, bq, pQ, PBS, PD, PD);
    tgemm_bias<<<dim3(KVW / TBN, PBS / TBM), 256>>>(x, wk, bk, pK, PBS, KVW, PD);
    tgemm_bias<<<dim3(KVW / TBN, PBS / TBM), 256>>>(x, wv, bv, pV, PBS, KVW, PD);

    // RoPE: Q gets the extra hd^-0.5 pre-scale; K plain.
    {
        int nq = PBS * PH * 64;
        rope_kernel<<<(nq + 255) / 256, 256>>>(pQ, PH, 0.08838834764831845f);
        int nk = PBS * PG * 64;
        rope_kernel<<<(nk + 255) / 256, 256>>>(pK, PG, 1.0f);
    }

    // attention
    flash_kernel<<<dim3(PS / FBR, PB * PH), 256, FLASH_SMEM>>>(pQ, pK, pV, pAO);

    // output projection
    tgemm_bias<<<dim3(PD / TBN, PBS / TBM), 256>>>(pAO, wo, bo, out, PBS, PD, PD);
}

// round 4
// speedup vs baseline: 3.0768x; 1.8212x over previous
#include <cuda_runtime.h>
#include <math.h>
#include <stdint.h>

// Problem constants
#define PB 4
#define PS 1024
#define PD 2048
#define PH 16
#define PG 2
#define PHD 128
#define PBS (PB * PS)          // 4096 rows
#define KVW (PG * PHD)         // 256

// ---------------- scratch (device globals; no allocation allowed) ----------
__device__ float g_Q[PBS * PD];        // 32 MB
__device__ float g_K[PBS * KVW];       // 4 MB
__device__ float g_V[PBS * KVW];       // 4 MB
__device__ float g_AO[PBS * PD];       // 32 MB

// ---------------- tf32 helpers ---------------------------------------------
__device__ __forceinline__ uint32_t f2tf(float x) {
    uint32_t r;
    asm("cvt.rna.tf32.f32 %0, %1;" : "=r"(r) : "f"(x));
    return r;
}

__device__ __forceinline__ void mma_tf32(float* d, const uint32_t* a, const uint32_t* b) {
    asm volatile(
        "mma.sync.aligned.m16n8k8.row.col.f32.tf32.tf32.f32 "
        "{%0,%1,%2,%3}, {%4,%5,%6,%7}, {%8,%9}, {%0,%1,%2,%3};\n"
        : "+f"(d[0]), "+f"(d[1]), "+f"(d[2]), "+f"(d[3])
        : "r"(a[0]), "r"(a[1]), "r"(a[2]), "r"(a[3]), "r"(b[0]), "r"(b[1]));
}

// ---------------- Tensor-core GEMM: C = A[M,K] @ W[K,N] + bias -------------
#define TBM 128
#define TBN 128
#define TBK 16
#define TSTR 136

__global__ __launch_bounds__(256, 2)
void tgemm_bias(const float* __restrict__ A, const float* __restrict__ W,
                const float* __restrict__ bias, float* __restrict__ C,
                int M, int N, int K) {
    __shared__ uint32_t As[TBK][TSTR];
    __shared__ uint32_t Bs[TBK][TSTR];

    const int tid  = threadIdx.x;
    const int lane = tid & 31;
    const int warp = tid >> 5;
    const int wm = (warp & 1) * 64;
    const int wn = (warp >> 1) * 32;
    const int bx = blockIdx.x;
    const int by = blockIdx.y;

    const int a_row = tid >> 2;
    const int a_c4  = tid & 3;
    const int b_row = tid >> 5;
    const int b_c4  = tid & 31;

    const float* Ap = A + (size_t)(by * TBM + a_row) * K + a_c4 * 4;
    const float* Bp = W + (size_t)b_row * N + bx * TBN + b_c4 * 4;

    float acc[4][4][4];
#pragma unroll
    for (int i = 0; i < 4; i++)
#pragma unroll
        for (int j = 0; j < 4; j++) {
            acc[i][j][0] = 0.f; acc[i][j][1] = 0.f;
            acc[i][j][2] = 0.f; acc[i][j][3] = 0.f;
        }

    float4 ar0 = *(const float4*)(Ap);
    float4 ar1 = *(const float4*)(Ap + (size_t)64 * K);
    float4 br0 = *(const float4*)(Bp);
    float4 br1 = *(const float4*)(Bp + (size_t)8 * N);

    for (int k0 = 0; k0 < K; k0 += TBK) {
        As[a_c4 * 4 + 0][a_row] = f2tf(ar0.x);
        As[a_c4 * 4 + 1][a_row] = f2tf(ar0.y);
        As[a_c4 * 4 + 2][a_row] = f2tf(ar0.z);
        As[a_c4 * 4 + 3][a_row] = f2tf(ar0.w);
        As[a_c4 * 4 + 0][a_row + 64] = f2tf(ar1.x);
        As[a_c4 * 4 + 1][a_row + 64] = f2tf(ar1.y);
        As[a_c4 * 4 + 2][a_row + 64] = f2tf(ar1.z);
        As[a_c4 * 4 + 3][a_row + 64] = f2tf(ar1.w);
        *(uint4*)&Bs[b_row][b_c4 * 4] =
            make_uint4(f2tf(br0.x), f2tf(br0.y), f2tf(br0.z), f2tf(br0.w));
        *(uint4*)&Bs[b_row + 8][b_c4 * 4] =
            make_uint4(f2tf(br1.x), f2tf(br1.y), f2tf(br1.z), f2tf(br1.w));
        __syncthreads();

        if (k0 + TBK < K) {
            ar0 = *(const float4*)(Ap + k0 + TBK);
            ar1 = *(const float4*)(Ap + k0 + TBK + (size_t)64 * K);
            br0 = *(const float4*)(Bp + (size_t)(k0 + TBK) * N);
            br1 = *(const float4*)(Bp + (size_t)(k0 + TBK + 8) * N);
        }

#pragma unroll
        for (int kk = 0; kk < TBK; kk += 8) {
            const int kq = kk + (lane & 3);
            const int gm = lane >> 2;
            uint32_t af[4][4];
#pragma unroll
            for (int mt = 0; mt < 4; mt++) {
                const int m0 = wm + mt * 16 + gm;
                af[mt][0] = As[kq][m0];
                af[mt][1] = As[kq][m0 + 8];
                af[mt][2] = As[kq + 4][m0];
                af[mt][3] = As[kq + 4][m0 + 8];
            }
            uint32_t bf[4][2];
#pragma unroll
            for (int nt = 0; nt < 4; nt++) {
                const int n0 = wn + nt * 8 + gm;
                bf[nt][0] = Bs[kq][n0];
                bf[nt][1] = Bs[kq + 4][n0];
            }
#pragma unroll
            for (int mt = 0; mt < 4; mt++)
#pragma unroll
                for (int nt = 0; nt < 4; nt++)
                    mma_tf32(acc[mt][nt], af[mt], bf[nt]);
        }
        __syncthreads();
    }

#pragma unroll
    for (int mt = 0; mt < 4; mt++) {
        const int row0 = by * TBM + wm + mt * 16 + (lane >> 2);
#pragma unroll
        for (int nt = 0; nt < 4; nt++) {
            const int col = bx * TBN + wn + nt * 8 + (lane & 3) * 2;
            const float b0 = bias[col], b1 = bias[col + 1];
            float2 v0, v1;
            v0.x = acc[mt][nt][0] + b0; v0.y = acc[mt][nt][1] + b1;
            v1.x = acc[mt][nt][2] + b0; v1.y = acc[mt][nt][3] + b1;
            *(float2*)(C + (size_t)row0 * N + col)       = v0;
            *(float2*)(C + (size_t)(row0 + 8) * N + col) = v1;
        }
    }
}

// ---------------- RoPE (in place) ------------------------------------------
__global__ void rope_kernel(float* __restrict__ data, int nheads, float outscale) {
    int idx = blockIdx.x * blockDim.x + threadIdx.x;
    int total = PBS * nheads * 64;
    if (idx >= total) return;
    int i   = idx & 63;
    int t   = idx >> 6;
    int hh  = t % nheads;
    int row = t / nheads;
    int s   = row & (PS - 1);

    float inv = powf(10000.f, -(float)i / 64.f);
    float ang = (float)s * inv;
    float sn, cs;
    sincosf(ang, &sn, &cs);

    float* p = data + (size_t)row * (nheads * PHD) + hh * PHD;
    float x1 = p[i];
    float x2 = p[i + 64];
    p[i]      = (x1 * cs - x2 * sn) * outscale;
    p[i + 64] = (x2 * cs + x1 * sn) * outscale;
}

// ---------------- Tensor-core flash attention ------------------------------
// 128 q-rows/CTA, Bc=64 keys/iter, 8 warps; warp w owns q-rows [w*16, w*16+16).
// All operands tf32 in smem; softmax stats warp-local (quad shuffles).
#define FM 128
#define FNC 64
#define QSTR 132   // mod 32 == 4 -> conflict-free row-indexed frag loads
#define KSTR 132
#define VSTR 136   // mod 32 == 8 -> conflict-free k-indexed frag loads
#define PSTR 68
#define FLASH_SMEM ((FM*QSTR + FNC*KSTR + FNC*VSTR + FM*PSTR) * 4)

__global__ __launch_bounds__(256, 1)
void flash_tc(const float* __restrict__ Q, const float* __restrict__ K,
              const float* __restrict__ V, float* __restrict__ O) {
    extern __shared__ uint32_t sm[];
    uint32_t* Qs = sm;                    // [FM][QSTR]
    uint32_t* Ks = Qs + FM * QSTR;        // [FNC][KSTR]
    uint32_t* Vs = Ks + FNC * KSTR;       // [FNC][VSTR]
    uint32_t* Ps = Vs + FNC * VSTR;       // [FM][PSTR]

    const int tid  = threadIdx.x;
    const int lane = tid & 31;
    const int warp = tid >> 5;
    const int wm   = warp * 16;
    const int r    = lane >> 2;           // 0..7
    const int q4   = lane & 3;            // 0..3

    const int qtile = blockIdx.x;         // 0..7
    const int bh = blockIdx.y;            // 0..63
    const int b = bh >> 4, h = bh & 15;
    const int g = h >> 3;                 // H/G = 8

    const float* Qb = Q + ((size_t)(b * PS + qtile * FM)) * PD + h * PHD;
    const float* Kb = K + ((size_t)(b * PS)) * KVW + g * PHD;
    const float* Vb = V + ((size_t)(b * PS)) * KVW + g * PHD;

    // load Q tile (128x128): 4096 float4 -> 16 per thread, tf32 convert
    for (int i = tid; i < FM * 32; i += 256) {
        int row = i >> 5, c4 = i & 31;
        float4 v = *(const float4*)(Qb + (size_t)row * PD + c4 * 4);
        *(uint4*)&Qs[row * QSTR + c4 * 4] =
            make_uint4(f2tf(v.x), f2tf(v.y), f2tf(v.z), f2tf(v.w));
    }

    float m[2] = {-INFINITY, -INFINITY};
    float l[2] = {0.f, 0.f};
    float oacc[16][4];
#pragma unroll
    for (int nt = 0; nt < 16; nt++) {
        oacc[nt][0] = 0.f; oacc[nt][1] = 0.f;
        oacc[nt][2] = 0.f; oacc[nt][3] = 0.f;
    }

    for (int k0 = 0; k0 < PS; k0 += FNC) {
        // load K,V tiles (64x128 each): 2048 f4 each -> 8/thread each
        for (int i = tid; i < FNC * 32; i += 256) {
            int row = i >> 5, c4 = i & 31;
            float4 kv = *(const float4*)(Kb + (size_t)(k0 + row) * KVW + c4 * 4);
            float4 vv = *(const float4*)(Vb + (size_t)(k0 + row) * KVW + c4 * 4);
            *(uint4*)&Ks[row * KSTR + c4 * 4] =
                make_uint4(f2tf(kv.x), f2tf(kv.y), f2tf(kv.z), f2tf(kv.w));
            *(uint4*)&Vs[row * VSTR + c4 * 4] =
                make_uint4(f2tf(vv.x), f2tf(vv.y), f2tf(vv.z), f2tf(vv.w));
        }
        __syncthreads();

        // S = Q @ K^T : warp computes 16x64
        float sacc[8][4];
#pragma unroll
        for (int nt = 0; nt < 8; nt++) {
            sacc[nt][0] = 0.f; sacc[nt][1] = 0.f;
            sacc[nt][2] = 0.f; sacc[nt][3] = 0.f;
        }
#pragma unroll
        for (int ks = 0; ks < 16; ks++) {
            const int kq = ks * 8 + q4;
            uint32_t a[4];
            a[0] = Qs[(wm + r) * QSTR + kq];
            a[1] = Qs[(wm + r + 8) * QSTR + kq];
            a[2] = Qs[(wm + r) * QSTR + kq + 4];
            a[3] = Qs[(wm + r + 8) * QSTR + kq + 4];
#pragma unroll
            for (int nt = 0; nt < 8; nt++) {
                uint32_t bfr[2];
                bfr[0] = Ks[(nt * 8 + r) * KSTR + kq];
                bfr[1] = Ks[(nt * 8 + r) * KSTR + kq + 4];
                mma_tf32(sacc[nt], a, bfr);
            }
        }

        // online softmax (rows rA = wm+r, rB = wm+r+8; scale folded into Q)
        float mxA = -INFINITY, mxB = -INFINITY;
#pragma unroll
        for (int nt = 0; nt < 8; nt++) {
            mxA = fmaxf(mxA, fmaxf(sacc[nt][0], sacc[nt][1]));
            mxB = fmaxf(mxB, fmaxf(sacc[nt][2], sacc[nt][3]));
        }
        mxA = fmaxf(mxA, __shfl_xor_sync(0xffffffffu, mxA, 1));
        mxA = fmaxf(mxA, __shfl_xor_sync(0xffffffffu, mxA, 2));
        mxB = fmaxf(mxB, __shfl_xor_sync(0xffffffffu, mxB, 1));
        mxB = fmaxf(mxB, __shfl_xor_sync(0xffffffffu, mxB, 2));

        const float mnA = fmaxf(m[0], mxA);
        const float mnB = fmaxf(m[1], mxB);
        const float alA = __expf(m[0] - mnA);
        const float alB = __expf(m[1] - mnB);

        float rsA = 0.f, rsB = 0.f;
#pragma unroll
        for (int nt = 0; nt < 8; nt++) {
            float p0 = __expf(sacc[nt][0] - mnA);
            float p1 = __expf(sacc[nt][1] - mnA);
            float p2 = __expf(sacc[nt][2] - mnB);
            float p3 = __expf(sacc[nt][3] - mnB);
            rsA += p0 + p1; rsB += p2 + p3;
            const int c = nt * 8 + q4 * 2;
            Ps[(wm + r) * PSTR + c]     = f2tf(p0);
            Ps[(wm + r) * PSTR + c + 1] = f2tf(p1);
            Ps[(wm + r + 8) * PSTR + c]     = f2tf(p2);
            Ps[(wm + r + 8) * PSTR + c + 1] = f2tf(p3);
        }
        rsA += __shfl_xor_sync(0xffffffffu, rsA, 1);
        rsA += __shfl_xor_sync(0xffffffffu, rsA, 2);
        rsB += __shfl_xor_sync(0xffffffffu, rsB, 1);
        rsB += __shfl_xor_sync(0xffffffffu, rsB, 2);

        l[0] = l[0] * alA + rsA;
        l[1] = l[1] * alB + rsB;
        m[0] = mnA; m[1] = mnB;
#pragma unroll
        for (int nt = 0; nt < 16; nt++) {
            oacc[nt][0] *= alA; oacc[nt][1] *= alA;
            oacc[nt][2] *= alB; oacc[nt][3] *= alB;
        }
        __syncwarp();

        // O += P @ V  (warp-local P rows)
#pragma unroll
        for (int ks = 0; ks < 8; ks++) {
            const int kq = ks * 8 + q4;
            uint32_t a[4];
            a[0] = Ps[(wm + r) * PSTR + kq];
            a[1] = Ps[(wm + r + 8) * PSTR + kq];
            a[2] = Ps[(wm + r) * PSTR + kq + 4];
            a[3] = Ps[(wm + r + 8) * PSTR + kq + 4];
#pragma unroll
            for (int nt = 0; nt < 16; nt++) {
                uint32_t bfr[2];
                bfr[0] = Vs[kq * VSTR + nt * 8 + r];
                bfr[1] = Vs[(kq + 4) * VSTR + nt * 8 + r];
                mma_tf32(oacc[nt], a, bfr);
            }
        }
        __syncthreads();
    }

    // epilogue: normalize + write
    const float ivA = 1.f / l[0];
    const float ivB = 1.f / l[1];
    const int rowA = qtile * FM + wm + r;
    float* opA = O + ((size_t)(b * PS + rowA)) * PD + h * PHD;
    float* opB = opA + (size_t)8 * PD;
#pragma unroll
    for (int nt = 0; nt < 16; nt++) {
        const int c = nt * 8 + q4 * 2;
        float2 vA, vB;
        vA.x = oacc[nt][0] * ivA; vA.y = oacc[nt][1] * ivA;
        vB.x = oacc[nt][2] * ivB; vB.y = oacc[nt][3] * ivB;
        *(float2*)(opA + c) = vA;
        *(float2*)(opB + c) = vB;
    }
}

// ---------------- launch ----------------------------------------------------
extern "C" void kernel_launch(void* const* d_in, const int* in_sizes, int n_in,
                              void* d_out, int out_size) {
    const float* x  = (const float*)d_in[0];
    const float* wq = (const float*)d_in[1];
    const float* bq = (const float*)d_in[2];
    const float* wk = (const float*)d_in[3];
    const float* bk = (const float*)d_in[4];
    const float* wv = (const float*)d_in[5];
    const float* bv = (const float*)d_in[6];
    const float* wo = (const float*)d_in[7];
    const float* bo = (const float*)d_in[8];
    float* out = (float*)d_out;

    float *pQ, *pK, *pV, *pAO;
    cudaGetSymbolAddress((void**)&pQ,  g_Q);
    cudaGetSymbolAddress((void**)&pK,  g_K);
    cudaGetSymbolAddress((void**)&pV,  g_V);
    cudaGetSymbolAddress((void**)&pAO, g_AO);

    cudaFuncSetAttribute(flash_tc, cudaFuncAttributeMaxDynamicSharedMemorySize,
                         (int)FLASH_SMEM);

    // QKV projections (tf32 tensor cores)
    tgemm_bias<<<dim3(PD / TBN, PBS / TBM), 256>>>(x, wq, bq, pQ, PBS, PD, PD);
    tgemm_bias<<<dim3(KVW / TBN, PBS / TBM), 256>>>(x, wk, bk, pK, PBS, KVW, PD);
    tgemm_bias<<<dim3(KVW / TBN, PBS / TBM), 256>>>(x, wv, bv, pV, PBS, KVW, PD);

    // RoPE: Q gets BOTH hd^-0.5 factors folded in (hd^-1 = 1/128); K plain.
    {
        int nq = PBS * PH * 64;
        rope_kernel<<<(nq + 255) / 256, 256>>>(pQ, PH, 0.0078125f);
        int nk = PBS * PG * 64;
        rope_kernel<<<(nk + 255) / 256, 256>>>(pK, PG, 1.0f);
    }

    // attention (tensor cores)
    flash_tc<<<dim3(PS / FM, PB * PH), 256, FLASH_SMEM>>>(pQ, pK, pV, pAO);

    // output projection
    tgemm_bias<<<dim3(PD / TBN, PBS / TBM), 256>>>(pAO, wo, bo, out, PBS, PD, PD);
}

// round 6
// speedup vs baseline: 6.0242x; 1.9579x over previous
#include <cuda_runtime.h>
#include <cuda_fp16.h>
#include <math.h>
#include <stdint.h>

// Problem constants
#define PB 4
#define PS 1024
#define PD 2048
#define PH 16
#define PG 2
#define PHD 128
#define PBS (PB * PS)          // 4096 rows
#define KVW (PG * PHD)         // 256

// ---------------- scratch (device globals; no allocation allowed) ----------
__device__ float  g_Q[PBS * PD];         // 32 MB
__device__ float  g_K[PBS * KVW];        // 4 MB
__device__ float  g_V[PBS * KVW];        // 4 MB
__device__ __half g_XH[PBS * PD];        // 16 MB (x, fp16)
__device__ __half g_AOH[PBS * PD];       // 16 MB (attn out, fp16)
__device__ __half g_WQT[PD * PD];        // 8 MB (wq^T fp16, [N][K])
__device__ __half g_WKT[KVW * PD];       // 1 MB
__device__ __half g_WVT[KVW * PD];       // 1 MB
__device__ __half g_WOT[PD * PD];        // 8 MB

// ---------------- helpers ---------------------------------------------------
__device__ __forceinline__ uint32_t f2tf(float x) {
    uint32_t r;
    asm("cvt.rna.tf32.f32 %0, %1;" : "=r"(r) : "f"(x));
    return r;
}

__device__ __forceinline__ void mma_tf32(float* d, const uint32_t* a, const uint32_t* b) {
    asm volatile(
        "mma.sync.aligned.m16n8k8.row.col.f32.tf32.tf32.f32 "
        "{%0,%1,%2,%3}, {%4,%5,%6,%7}, {%8,%9}, {%0,%1,%2,%3};\n"
        : "+f"(d[0]), "+f"(d[1]), "+f"(d[2]), "+f"(d[3])
        : "r"(a[0]), "r"(a[1]), "r"(a[2]), "r"(a[3]), "r"(b[0]), "r"(b[1]));
}

__device__ __forceinline__ void mma_f16(float* d, const uint32_t* a, const uint32_t* b) {
    asm volatile(
        "mma.sync.aligned.m16n8k16.row.col.f32.f16.f16.f32 "
        "{%0,%1,%2,%3}, {%4,%5,%6,%7}, {%8,%9}, {%0,%1,%2,%3};\n"
        : "+f"(d[0]), "+f"(d[1]), "+f"(d[2]), "+f"(d[3])
        : "r"(a[0]), "r"(a[1]), "r"(a[2]), "r"(a[3]), "r"(b[0]), "r"(b[1]));
}

__device__ __forceinline__ void ldsm4(uint32_t* r, uint32_t addr) {
    asm volatile(
        "ldmatrix.sync.aligned.m8n8.x4.shared.b16 {%0,%1,%2,%3}, [%4];"
        : "=r"(r[0]), "=r"(r[1]), "=r"(r[2]), "=r"(r[3]) : "r"(addr));
}

__device__ __forceinline__ uint32_t smem_u32(const void* p) {
    return (uint32_t)__cvta_generic_to_shared(p);
}

__device__ __forceinline__ void cp16(uint32_t dst, const void* src) {
    asm volatile("cp.async.cg.shared.global [%0], [%1], 16;\n" :: "r"(dst), "l"(src));
}

// ---------------- prep kernels ----------------------------------------------
// float -> half, 8 elements per thread
__global__ void cvt_h_kernel(const float* __restrict__ X, __half* __restrict__ Y, int n8) {
    int i = blockIdx.x * 256 + threadIdx.x;
    if (i >= n8) return;
    float4 a = ((const float4*)X)[2 * i];
    float4 b = ((const float4*)X)[2 * i + 1];
    __half2 h0 = __floats2half2_rn(a.x, a.y);
    __half2 h1 = __floats2half2_rn(a.z, a.w);
    __half2 h2 = __floats2half2_rn(b.x, b.y);
    __half2 h3 = __floats2half2_rn(b.z, b.w);
    uint4 u;
    u.x = *(uint32_t*)&h0; u.y = *(uint32_t*)&h1;
    u.z = *(uint32_t*)&h2; u.w = *(uint32_t*)&h3;
    ((uint4*)Y)[i] = u;
}

// W[K][N] (f32) -> WT[N][K] (fp16)
__global__ void transpose_h(const float* __restrict__ W, __half* __restrict__ WT,
                            int K, int N) {
    __shared__ float t[32][33];
    int k0 = blockIdx.y * 32, n0 = blockIdx.x * 32;
    int tx = threadIdx.x, ty = threadIdx.y;  // 32 x 8
#pragma unroll
    for (int j = 0; j < 32; j += 8)
        t[ty + j][tx] = W[(size_t)(k0 + ty + j) * N + n0 + tx];
    __syncthreads();
#pragma unroll
    for (int j = 0; j < 32; j += 8)
        WT[(size_t)(n0 + ty + j) * K + k0 + tx] = __float2half_rn(t[tx][ty + j]);
}

// ---------------- fp16 tensor GEMM: C[M,N] = A[M,2048] @ BT[N,2048]^T + bias
// CTA tile 128x128, BK=64 halves (128B rows), double-buffered cp.async,
// XOR-swizzled smem + ldmatrix.x4 fragment loads, mma m16n8k16.
#define GK 2048
#define HNIT (GK / 64)
#define HSMEM 65536

__global__ __launch_bounds__(256, 2)
void tgemm_h(const __half* __restrict__ A, const __half* __restrict__ BT,
             const float* __restrict__ bias, float* __restrict__ C, int N) {
    extern __shared__ char smem[];
    const uint32_t sbase = smem_u32(smem);
    const int tid  = threadIdx.x;
    const int lane = tid & 31;
    const int warp = tid >> 5;
    const int wm = (warp & 1) * 64;
    const int wn = (warp >> 1) * 32;
    const int m0 = blockIdx.y * 128;
    const int n0 = blockIdx.x * 128;

    const uint32_t abuf[2] = {sbase,         sbase + 16384};
    const uint32_t bbuf[2] = {sbase + 32768, sbase + 49152};

    const __half* Ag = A  + (size_t)m0 * GK;
    const __half* Bg = BT + (size_t)n0 * GK;

    // stage one 128x64h tile (128 rows x 128B, SW: chunk ^= row&7)
#define STAGE(buf, Gp, kc) do {                                                 \
    _Pragma("unroll")                                                           \
    for (int i_ = 0; i_ < 4; i_++) {                                            \
        int e_ = tid + 256 * i_;                                                \
        int row_ = e_ >> 3, j_ = e_ & 7;                                        \
        uint32_t dst_ = (buf) + row_ * 128 + ((j_ ^ (row_ & 7)) * 16);          \
        cp16(dst_, (Gp) + (size_t)row_ * GK + (kc) + j_ * 8);                   \
    } } while (0)

    float acc[4][4][4];
#pragma unroll
    for (int i = 0; i < 4; i++)
#pragma unroll
        for (int j = 0; j < 4; j++) {
            acc[i][j][0] = 0.f; acc[i][j][1] = 0.f;
            acc[i][j][2] = 0.f; acc[i][j][3] = 0.f;
        }

    STAGE(abuf[0], Ag, 0); STAGE(bbuf[0], Bg, 0);
    asm volatile("cp.async.commit_group;" ::: "memory");
    STAGE(abuf[1], Ag, 64); STAGE(bbuf[1], Bg, 64);
    asm volatile("cp.async.commit_group;" ::: "memory");

    for (int it = 0; it < HNIT; ++it) {
        const int b = it & 1;
        if (it < HNIT - 1)
            asm volatile("cp.async.wait_group 1;" ::: "memory");
        else
            asm volatile("cp.async.wait_group 0;" ::: "memory");
        __syncthreads();

        // fragment addresses (A: row=m-row, B: row=n-row; both k-contiguous)
        const int arow = wm + (lane & 15);
        const int brow0 = wn + ((lane >> 4) << 3) + (lane & 7);
#pragma unroll
        for (int s = 0; s < 4; ++s) {
            uint32_t af[4][4];
#pragma unroll
            for (int mt = 0; mt < 4; mt++) {
                const int row = arow + mt * 16;
                const int ch = (s * 2 + (lane >> 4)) ^ (row & 7);
                ldsm4(af[mt], abuf[b] + row * 128 + ch * 16);
            }
            uint32_t bf[4][2];
#pragma unroll
            for (int nth = 0; nth < 2; nth++) {
                const int row = brow0 + nth * 16;
                const int ch = (s * 2 + ((lane >> 3) & 1)) ^ (row & 7);
                uint32_t r4[4];
                ldsm4(r4, bbuf[b] + row * 128 + ch * 16);
                bf[nth * 2][0] = r4[0]; bf[nth * 2][1] = r4[1];
                bf[nth * 2 + 1][0] = r4[2]; bf[nth * 2 + 1][1] = r4[3];
            }
#pragma unroll
            for (int mt = 0; mt < 4; mt++)
#pragma unroll
                for (int nt = 0; nt < 4; nt++)
                    mma_f16(acc[mt][nt], af[mt], bf[nt]);
        }
        __syncthreads();

        if (it + 2 < HNIT) {
            STAGE(abuf[b], Ag, (it + 2) * 64);
            STAGE(bbuf[b], Bg, (it + 2) * 64);
            asm volatile("cp.async.commit_group;" ::: "memory");
        }
    }

    // epilogue with bias
#pragma unroll
    for (int mt = 0; mt < 4; mt++) {
        const int row0 = m0 + wm + mt * 16 + (lane >> 2);
#pragma unroll
        for (int nt = 0; nt < 4; nt++) {
            const int col = n0 + wn + nt * 8 + (lane & 3) * 2;
            const float b0 = bias[col], b1 = bias[col + 1];
            float2 v0, v1;
            v0.x = acc[mt][nt][0] + b0; v0.y = acc[mt][nt][1] + b1;
            v1.x = acc[mt][nt][2] + b0; v1.y = acc[mt][nt][3] + b1;
            *(float2*)(C + (size_t)row0 * N + col)       = v0;
            *(float2*)(C + (size_t)(row0 + 8) * N + col) = v1;
        }
    }
}

// ---------------- RoPE (in place) ------------------------------------------
__global__ void rope_kernel(float* __restrict__ data, int nheads, float outscale) {
    int idx = blockIdx.x * blockDim.x + threadIdx.x;
    int total = PBS * nheads * 64;
    if (idx >= total) return;
    int i   = idx & 63;
    int t   = idx >> 6;
    int hh  = t % nheads;
    int row = t / nheads;
    int s   = row & (PS - 1);

    float inv = powf(10000.f, -(float)i / 64.f);
    float ang = (float)s * inv;
    float sn, cs;
    sincosf(ang, &sn, &cs);

    float* p = data + (size_t)row * (nheads * PHD) + hh * PHD;
    float x1 = p[i];
    float x2 = p[i + 64];
    p[i]      = (x1 * cs - x2 * sn) * outscale;
    p[i + 64] = (x2 * cs + x1 * sn) * outscale;
}

// ---------------- Tensor-core flash attention (tf32 mma.sync) --------------
#define FM 128
#define FNC 64
#define QSTR 132
#define KSTR 132
#define VSTR 136
#define PSTR 68
#define FLASH_SMEM ((FM*QSTR + FNC*KSTR + FNC*VSTR + FM*PSTR) * 4)

__global__ __launch_bounds__(256, 1)
void flash_tc(const float* __restrict__ Q, const float* __restrict__ K,
              const float* __restrict__ V, __half* __restrict__ O) {
    extern __shared__ uint32_t sm[];
    uint32_t* Qs = sm;
    uint32_t* Ks = Qs + FM * QSTR;
    uint32_t* Vs = Ks + FNC * KSTR;
    uint32_t* Ps = Vs + FNC * VSTR;

    const int tid  = threadIdx.x;
    const int lane = tid & 31;
    const int warp = tid >> 5;
    const int wm   = warp * 16;
    const int r    = lane >> 2;
    const int q4   = lane & 3;

    const int qtile = blockIdx.x;
    const int bh = blockIdx.y;
    const int b = bh >> 4, h = bh & 15;
    const int g = h >> 3;

    const float* Qb = Q + ((size_t)(b * PS + qtile * FM)) * PD + h * PHD;
    const float* Kb = K + ((size_t)(b * PS)) * KVW + g * PHD;
    const float* Vb = V + ((size_t)(b * PS)) * KVW + g * PHD;

    for (int i = tid; i < FM * 32; i += 256) {
        int row = i >> 5, c4 = i & 31;
        float4 v = *(const float4*)(Qb + (size_t)row * PD + c4 * 4);
        *(uint4*)&Qs[row * QSTR + c4 * 4] =
            make_uint4(f2tf(v.x), f2tf(v.y), f2tf(v.z), f2tf(v.w));
    }

    float m[2] = {-INFINITY, -INFINITY};
    float l[2] = {0.f, 0.f};
    float oacc[16][4];
#pragma unroll
    for (int nt = 0; nt < 16; nt++) {
        oacc[nt][0] = 0.f; oacc[nt][1] = 0.f;
        oacc[nt][2] = 0.f; oacc[nt][3] = 0.f;
    }

    for (int k0 = 0; k0 < PS; k0 += FNC) {
        for (int i = tid; i < FNC * 32; i += 256) {
            int row = i >> 5, c4 = i & 31;
            float4 kv = *(const float4*)(Kb + (size_t)(k0 + row) * KVW + c4 * 4);
            float4 vv = *(const float4*)(Vb + (size_t)(k0 + row) * KVW + c4 * 4);
            *(uint4*)&Ks[row * KSTR + c4 * 4] =
                make_uint4(f2tf(kv.x), f2tf(kv.y), f2tf(kv.z), f2tf(kv.w));
            *(uint4*)&Vs[row * VSTR + c4 * 4] =
                make_uint4(f2tf(vv.x), f2tf(vv.y), f2tf(vv.z), f2tf(vv.w));
        }
        __syncthreads();

        float sacc[8][4];
#pragma unroll
        for (int nt = 0; nt < 8; nt++) {
            sacc[nt][0] = 0.f; sacc[nt][1] = 0.f;
            sacc[nt][2] = 0.f; sacc[nt][3] = 0.f;
        }
#pragma unroll
        for (int ks = 0; ks < 16; ks++) {
            const int kq = ks * 8 + q4;
            uint32_t a[4];
            a[0] = Qs[(wm + r) * QSTR + kq];
            a[1] = Qs[(wm + r + 8) * QSTR + kq];
            a[2] = Qs[(wm + r) * QSTR + kq + 4];
            a[3] = Qs[(wm + r + 8) * QSTR + kq + 4];
#pragma unroll
            for (int nt = 0; nt < 8; nt++) {
                uint32_t bfr[2];
                bfr[0] = Ks[(nt * 8 + r) * KSTR + kq];
                bfr[1] = Ks[(nt * 8 + r) * KSTR + kq + 4];
                mma_tf32(sacc[nt], a, bfr);
            }
        }

        float mxA = -INFINITY, mxB = -INFINITY;
#pragma unroll
        for (int nt = 0; nt < 8; nt++) {
            mxA = fmaxf(mxA, fmaxf(sacc[nt][0], sacc[nt][1]));
            mxB = fmaxf(mxB, fmaxf(sacc[nt][2], sacc[nt][3]));
        }
        mxA = fmaxf(mxA, __shfl_xor_sync(0xffffffffu, mxA, 1));
        mxA = fmaxf(mxA, __shfl_xor_sync(0xffffffffu, mxA, 2));
        mxB = fmaxf(mxB, __shfl_xor_sync(0xffffffffu, mxB, 1));
        mxB = fmaxf(mxB, __shfl_xor_sync(0xffffffffu, mxB, 2));

        const float mnA = fmaxf(m[0], mxA);
        const float mnB = fmaxf(m[1], mxB);
        const float alA = __expf(m[0] - mnA);
        const float alB = __expf(m[1] - mnB);

        float rsA = 0.f, rsB = 0.f;
#pragma unroll
        for (int nt = 0; nt < 8; nt++) {
            float p0 = __expf(sacc[nt][0] - mnA);
            float p1 = __expf(sacc[nt][1] - mnA);
            float p2 = __expf(sacc[nt][2] - mnB);
            float p3 = __expf(sacc[nt][3] - mnB);
            rsA += p0 + p1; rsB += p2 + p3;
            const int c = nt * 8 + q4 * 2;
            Ps[(wm + r) * PSTR + c]     = f2tf(p0);
            Ps[(wm + r) * PSTR + c + 1] = f2tf(p1);
            Ps[(wm + r + 8) * PSTR + c]     = f2tf(p2);
            Ps[(wm + r + 8) * PSTR + c + 1] = f2tf(p3);
        }
        rsA += __shfl_xor_sync(0xffffffffu, rsA, 1);
        rsA += __shfl_xor_sync(0xffffffffu, rsA, 2);
        rsB += __shfl_xor_sync(0xffffffffu, rsB, 1);
        rsB += __shfl_xor_sync(0xffffffffu, rsB, 2);

        l[0] = l[0] * alA + rsA;
        l[1] = l[1] * alB + rsB;
        m[0] = mnA; m[1] = mnB;
#pragma unroll
        for (int nt = 0; nt < 16; nt++) {
            oacc[nt][0] *= alA; oacc[nt][1] *= alA;
            oacc[nt][2] *= alB; oacc[nt][3] *= alB;
        }
        __syncwarp();

#pragma unroll
        for (int ks = 0; ks < 8; ks++) {
            const int kq = ks * 8 + q4;
            uint32_t a[4];
            a[0] = Ps[(wm + r) * PSTR + kq];
            a[1] = Ps[(wm + r + 8) * PSTR + kq];
            a[2] = Ps[(wm + r) * PSTR + kq + 4];
            a[3] = Ps[(wm + r + 8) * PSTR + kq + 4];
#pragma unroll
            for (int nt = 0; nt < 16; nt++) {
                uint32_t bfr[2];
                bfr[0] = Vs[kq * VSTR + nt * 8 + r];
                bfr[1] = Vs[(kq + 4) * VSTR + nt * 8 + r];
                mma_tf32(oacc[nt], a, bfr);
            }
        }
        __syncthreads();
    }

    // epilogue: normalize, write fp16 (feeds the fp16 O-projection directly)
    const float ivA = 1.f / l[0];
    const float ivB = 1.f / l[1];
    const int rowA = qtile * FM + wm + r;
    __half* opA = O + ((size_t)(b * PS + rowA)) * PD + h * PHD;
    __half* opB = opA + (size_t)8 * PD;
#pragma unroll
    for (int nt = 0; nt < 16; nt++) {
        const int c = nt * 8 + q4 * 2;
        __half2 hA = __floats2half2_rn(oacc[nt][0] * ivA, oacc[nt][1] * ivA);
        __half2 hB = __floats2half2_rn(oacc[nt][2] * ivB, oacc[nt][3] * ivB);
        *(__half2*)(opA + c) = hA;
        *(__half2*)(opB + c) = hB;
    }
}

// ---------------- launch ----------------------------------------------------
extern "C" void kernel_launch(void* const* d_in, const int* in_sizes, int n_in,
                              void* d_out, int out_size) {
    const float* x  = (const float*)d_in[0];
    const float* wq = (const float*)d_in[1];
    const float* bq = (const float*)d_in[2];
    const float* wk = (const float*)d_in[3];
    const float* bk = (const float*)d_in[4];
    const float* wv = (const float*)d_in[5];
    const float* bv = (const float*)d_in[6];
    const float* wo = (const float*)d_in[7];
    const float* bo = (const float*)d_in[8];
    float* out = (float*)d_out;

    float *pQ, *pK, *pV;
    __half *pXH, *pAOH, *pWQT, *pWKT, *pWVT, *pWOT;
    cudaGetSymbolAddress((void**)&pQ,   g_Q);
    cudaGetSymbolAddress((void**)&pK,   g_K);
    cudaGetSymbolAddress((void**)&pV,   g_V);
    cudaGetSymbolAddress((void**)&pXH,  g_XH);
    cudaGetSymbolAddress((void**)&pAOH, g_AOH);
    cudaGetSymbolAddress((void**)&pWQT, g_WQT);
    cudaGetSymbolAddress((void**)&pWKT, g_WKT);
    cudaGetSymbolAddress((void**)&pWVT, g_WVT);
    cudaGetSymbolAddress((void**)&pWOT, g_WOT);

    cudaFuncSetAttribute(flash_tc, cudaFuncAttributeMaxDynamicSharedMemorySize,
                         (int)FLASH_SMEM);
    cudaFuncSetAttribute(tgemm_h, cudaFuncAttributeMaxDynamicSharedMemorySize,
                         (int)HSMEM);

    // prep: x -> fp16; weights -> fp16 transposed [N][K]
    {
        int n8 = PBS * PD / 8;
        cvt_h_kernel<<<(n8 + 255) / 256, 256>>>(x, pXH, n8);
        transpose_h<<<dim3(PD / 32, PD / 32),  dim3(32, 8)>>>(wq, pWQT, PD, PD);
        transpose_h<<<dim3(KVW / 32, PD / 32), dim3(32, 8)>>>(wk, pWKT, PD, KVW);
        transpose_h<<<dim3(KVW / 32, PD / 32), dim3(32, 8)>>>(wv, pWVT, PD, KVW);
        transpose_h<<<dim3(PD / 32, PD / 32),  dim3(32, 8)>>>(wo, pWOT, PD, PD);
    }

    // QKV projections (fp16 tensor cores)
    tgemm_h<<<dim3(PD / 128, PBS / 128),  256, HSMEM>>>(pXH, pWQT, bq, pQ, PD);
    tgemm_h<<<dim3(KVW / 128, PBS / 128), 256, HSMEM>>>(pXH, pWKT, bk, pK, KVW);
    tgemm_h<<<dim3(KVW / 128, PBS / 128), 256, HSMEM>>>(pXH, pWVT, bv, pV, KVW);

    // RoPE: Q gets BOTH hd^-0.5 factors folded in (hd^-1 = 1/128); K plain.
    {
        int nq = PBS * PH * 64;
        rope_kernel<<<(nq + 255) / 256, 256>>>(pQ, PH, 0.0078125f);
        int nk = PBS * PG * 64;
        rope_kernel<<<(nk + 255) / 256, 256>>>(pK, PG, 1.0f);
    }

    // attention (tf32 tensor cores), writes fp16
    flash_tc<<<dim3(PS / FM, PB * PH), 256, FLASH_SMEM>>>(pQ, pK, pV, pAOH);

    // output projection (fp16 tensor cores)
    tgemm_h<<<dim3(PD / 128, PBS / 128), 256, HSMEM>>>(pAOH, pWOT, bo, out, PD);
}

// round 8
// speedup vs baseline: 9.1952x; 1.5264x over previous
#include <cuda_runtime.h>
#include <cuda_fp16.h>
#include <math.h>
#include <stdint.h>

// Problem constants
#define PB 4
#define PS 1024
#define PD 2048
#define PH 16
#define PG 2
#define PHD 128
#define PBS (PB * PS)          // 4096 rows
#define KVW (PG * PHD)         // 256
#define NQKV 2560              // 2048 + 256 + 256

// ---------------- scratch (device globals; no allocation allowed) ----------
__device__ float  g_Q[PBS * PD];         // 32 MB (f32 Q pre-rope)
__device__ float  g_K[PBS * KVW];        // 4 MB (f32 K pre-rope)
__device__ __half g_QH[PBS * PD];        // 16 MB (Q post-rope fp16)
__device__ __half g_KH[PBS * KVW];       // 2 MB
__device__ __half g_VH[PBS * KVW];       // 2 MB
__device__ __half g_XH[PBS * PD];        // 16 MB (x fp16)
__device__ __half g_AOH[PBS * PD];       // 16 MB (attn out fp16)
__device__ __half g_WCT[NQKV * PD];      // 10 MB (wq|wk|wv ^T fp16 [N][K])
__device__ __half g_WOT[PD * PD];        // 8 MB
__device__ float  g_BC[NQKV];

// ---------------- helpers ---------------------------------------------------
__device__ __forceinline__ void mma_f16(float* d, const uint32_t* a, const uint32_t* b) {
    asm volatile(
        "mma.sync.aligned.m16n8k16.row.col.f32.f16.f16.f32 "
        "{%0,%1,%2,%3}, {%4,%5,%6,%7}, {%8,%9}, {%0,%1,%2,%3};\n"
        : "+f"(d[0]), "+f"(d[1]), "+f"(d[2]), "+f"(d[3])
        : "r"(a[0]), "r"(a[1]), "r"(a[2]), "r"(a[3]), "r"(b[0]), "r"(b[1]));
}

__device__ __forceinline__ void ldsm4(uint32_t* r, uint32_t addr) {
    asm volatile(
        "ldmatrix.sync.aligned.m8n8.x4.shared.b16 {%0,%1,%2,%3}, [%4];"
        : "=r"(r[0]), "=r"(r[1]), "=r"(r[2]), "=r"(r[3]) : "r"(addr));
}
__device__ __forceinline__ void ldsm4t(uint32_t* r, uint32_t addr) {
    asm volatile(
        "ldmatrix.sync.aligned.m8n8.x4.trans.shared.b16 {%0,%1,%2,%3}, [%4];"
        : "=r"(r[0]), "=r"(r[1]), "=r"(r[2]), "=r"(r[3]) : "r"(addr));
}

__device__ __forceinline__ uint32_t smem_u32(const void* p) {
    return (uint32_t)__cvta_generic_to_shared(p);
}
__device__ __forceinline__ void cp16(uint32_t dst, const void* src) {
    asm volatile("cp.async.cg.shared.global [%0], [%1], 16;\n" :: "r"(dst), "l"(src));
}

// XOR swizzles: 256B rows (16x16B chunks) and 128B rows (8x16B chunks)
__device__ __forceinline__ uint32_t swz256(int row, int j) {
    return (uint32_t)(row * 256 + (((((j) & 7) ^ (row & 7)) | ((j) & 8)) * 16));
}
__device__ __forceinline__ uint32_t swz128(int row, int j) {
    return (uint32_t)(row * 128 + (((j) ^ (row & 7)) * 16));
}

// ---------------- prep kernels ----------------------------------------------
__global__ void cvt_h_kernel(const float* __restrict__ X, __half* __restrict__ Y, int n8) {
    int i = blockIdx.x * 256 + threadIdx.x;
    if (i >= n8) return;
    float4 a = ((const float4*)X)[2 * i];
    float4 b = ((const float4*)X)[2 * i + 1];
    __half2 h0 = __floats2half2_rn(a.x, a.y);
    __half2 h1 = __floats2half2_rn(a.z, a.w);
    __half2 h2 = __floats2half2_rn(b.x, b.y);
    __half2 h3 = __floats2half2_rn(b.z, b.w);
    uint4 u;
    u.x = *(uint32_t*)&h0; u.y = *(uint32_t*)&h1;
    u.z = *(uint32_t*)&h2; u.w = *(uint32_t*)&h3;
    ((uint4*)Y)[i] = u;
}

// W[K][N] (f32) -> WT[N][K] (fp16)
__global__ void transpose_h(const float* __restrict__ W, __half* __restrict__ WT,
                            int K, int N) {
    __shared__ float t[32][33];
    int k0 = blockIdx.y * 32, n0 = blockIdx.x * 32;
    int tx = threadIdx.x, ty = threadIdx.y;  // 32 x 8
#pragma unroll
    for (int j = 0; j < 32; j += 8)
        t[ty + j][tx] = W[(size_t)(k0 + ty + j) * N + n0 + tx];
    __syncthreads();
#pragma unroll
    for (int j = 0; j < 32; j += 8)
        WT[(size_t)(n0 + ty + j) * K + k0 + tx] = __float2half_rn(t[tx][ty + j]);
}

__global__ void concat_bias(const float* __restrict__ bq, const float* __restrict__ bk,
                            const float* __restrict__ bv, float* __restrict__ bc) {
    int i = blockIdx.x * 256 + threadIdx.x;
    if (i < 2048) bc[i] = bq[i];
    else if (i < 2304) bc[i] = bk[i - 2048];
    else if (i < NQKV) bc[i] = bv[i - 2304];
}

// ---------------- fp16 tensor GEMM core (128x128 tile, BK=64) ---------------
#define GK 2048
#define HNIT (GK / 64)
#define HSMEM 65536

#define STAGE(buf, Gp, kc) do {                                                 \
    _Pragma("unroll")                                                           \
    for (int i_ = 0; i_ < 4; i_++) {                                            \
        int e_ = tid + 256 * i_;                                                \
        int row_ = e_ >> 3, j_ = e_ & 7;                                        \
        uint32_t dst_ = (buf) + row_ * 128 + ((j_ ^ (row_ & 7)) * 16);          \
        cp16(dst_, (Gp) + (size_t)row_ * GK + (kc) + j_ * 8);                   \
    } } while (0)

#define GEMM_MAIN(ACC)                                                          \
    STAGE(abuf[0], Ag, 0); STAGE(bbuf[0], Bg, 0);                               \
    asm volatile("cp.async.commit_group;" ::: "memory");                        \
    STAGE(abuf[1], Ag, 64); STAGE(bbuf[1], Bg, 64);                             \
    asm volatile("cp.async.commit_group;" ::: "memory");                        \
    for (int it = 0; it < HNIT; ++it) {                                         \
        const int bb = it & 1;                                                  \
        if (it < HNIT - 1)                                                      \
            asm volatile("cp.async.wait_group 1;" ::: "memory");                \
        else                                                                    \
            asm volatile("cp.async.wait_group 0;" ::: "memory");                \
        __syncthreads();                                                        \
        const int arow = wm + (lane & 15);                                      \
        const int brow0 = wn + ((lane >> 4) << 3) + (lane & 7);                 \
        _Pragma("unroll")                                                       \
        for (int s = 0; s < 4; ++s) {                                           \
            uint32_t af[4][4];                                                  \
            _Pragma("unroll")                                                   \
            for (int mt = 0; mt < 4; mt++) {                                    \
                const int row = arow + mt * 16;                                 \
                const int ch = (s * 2 + (lane >> 4)) ^ (row & 7);               \
                ldsm4(af[mt], abuf[bb] + row * 128 + ch * 16);                  \
            }                                                                   \
            uint32_t bf[4][2];                                                  \
            _Pragma("unroll")                                                   \
            for (int nth = 0; nth < 2; nth++) {                                 \
                const int row = brow0 + nth * 16;                               \
                const int ch = (s * 2 + ((lane >> 3) & 1)) ^ (row & 7);         \
                uint32_t r4[4];                                                 \
                ldsm4(r4, bbuf[bb] + row * 128 + ch * 16);                      \
                bf[nth * 2][0] = r4[0]; bf[nth * 2][1] = r4[1];                 \
                bf[nth * 2 + 1][0] = r4[2]; bf[nth * 2 + 1][1] = r4[3];         \
            }                                                                   \
            _Pragma("unroll")                                                   \
            for (int mt = 0; mt < 4; mt++)                                      \
                _Pragma("unroll")                                               \
                for (int nt = 0; nt < 4; nt++)                                  \
                    mma_f16(ACC[mt][nt], af[mt], bf[nt]);                       \
        }                                                                       \
        __syncthreads();                                                        \
        if (it + 2 < HNIT) {                                                    \
            STAGE(abuf[bb], Ag, (it + 2) * 64);                                 \
            STAGE(bbuf[bb], Bg, (it + 2) * 64);                                 \
            asm volatile("cp.async.commit_group;" ::: "memory");                \
        }                                                                       \
    }

// O-projection GEMM: f32 out
__global__ __launch_bounds__(256, 2)
void tgemm_h(const __half* __restrict__ A, const __half* __restrict__ BT,
             const float* __restrict__ bias, float* __restrict__ C, int N) {
    extern __shared__ char smem[];
    const uint32_t sbase = smem_u32(smem);
    const int tid  = threadIdx.x;
    const int lane = tid & 31;
    const int warp = tid >> 5;
    const int wm = (warp & 1) * 64;
    const int wn = (warp >> 1) * 32;
    const int m0 = blockIdx.y * 128;
    const int n0 = blockIdx.x * 128;

    const uint32_t abuf[2] = {sbase,         sbase + 16384};
    const uint32_t bbuf[2] = {sbase + 32768, sbase + 49152};
    const __half* Ag = A  + (size_t)m0 * GK;
    const __half* Bg = BT + (size_t)n0 * GK;

    float acc[4][4][4];
#pragma unroll
    for (int i = 0; i < 4; i++)
#pragma unroll
        for (int j = 0; j < 4; j++)
            acc[i][j][0] = acc[i][j][1] = acc[i][j][2] = acc[i][j][3] = 0.f;

    GEMM_MAIN(acc)

#pragma unroll
    for (int mt = 0; mt < 4; mt++) {
        const int row0 = m0 + wm + mt * 16 + (lane >> 2);
#pragma unroll
        for (int nt = 0; nt < 4; nt++) {
            const int col = n0 + wn + nt * 8 + (lane & 3) * 2;
            const float b0 = bias[col], b1 = bias[col + 1];
            float2 v0, v1;
            v0.x = acc[mt][nt][0] + b0; v0.y = acc[mt][nt][1] + b1;
            v1.x = acc[mt][nt][2] + b0; v1.y = acc[mt][nt][3] + b1;
            *(float2*)(C + (size_t)row0 * N + col)       = v0;
            *(float2*)(C + (size_t)(row0 + 8) * N + col) = v1;
        }
    }
}

// Fused QKV GEMM: N=2560, routed epilogue (Q f32 / K f32 / V fp16)
__global__ __launch_bounds__(256, 2)
void tgemm_qkv(const __half* __restrict__ A, const __half* __restrict__ BT,
               const float* __restrict__ bias, float* __restrict__ Qo,
               float* __restrict__ Ko, __half* __restrict__ Vo) {
    extern __shared__ char smem[];
    const uint32_t sbase = smem_u32(smem);
    const int tid  = threadIdx.x;
    const int lane = tid & 31;
    const int warp = tid >> 5;
    const int wm = (warp & 1) * 64;
    const int wn = (warp >> 1) * 32;
    const int m0 = blockIdx.y * 128;
    const int n0 = blockIdx.x * 128;

    const uint32_t abuf[2] = {sbase,         sbase + 16384};
    const uint32_t bbuf[2] = {sbase + 32768, sbase + 49152};
    const __half* Ag = A  + (size_t)m0 * GK;
    const __half* Bg = BT + (size_t)n0 * GK;

    float acc[4][4][4];
#pragma unroll
    for (int i = 0; i < 4; i++)
#pragma unroll
        for (int j = 0; j < 4; j++)
            acc[i][j][0] = acc[i][j][1] = acc[i][j][2] = acc[i][j][3] = 0.f;

    GEMM_MAIN(acc)

#pragma unroll
    for (int mt = 0; mt < 4; mt++) {
        const int row0 = m0 + wm + mt * 16 + (lane >> 2);
#pragma unroll
        for (int nt = 0; nt < 4; nt++) {
            const int col = n0 + wn + nt * 8 + (lane & 3) * 2;
            const float b0 = bias[col], b1 = bias[col + 1];
            float c00 = acc[mt][nt][0] + b0, c01 = acc[mt][nt][1] + b1;
            float c10 = acc[mt][nt][2] + b0, c11 = acc[mt][nt][3] + b1;
            if (n0 < 2048) {
                *(float2*)(Qo + (size_t)row0 * PD + col)       = make_float2(c00, c01);
                *(float2*)(Qo + (size_t)(row0 + 8) * PD + col) = make_float2(c10, c11);
            } else if (n0 < 2304) {
                const int c = col - 2048;
                *(float2*)(Ko + (size_t)row0 * KVW + c)       = make_float2(c00, c01);
                *(float2*)(Ko + (size_t)(row0 + 8) * KVW + c) = make_float2(c10, c11);
            } else {
                const int c = col - 2304;
                *(__half2*)(Vo + (size_t)row0 * KVW + c)       = __floats2half2_rn(c00, c01);
                *(__half2*)(Vo + (size_t)(row0 + 8) * KVW + c) = __floats2half2_rn(c10, c11);
            }
        }
    }
}

// ---------------- RoPE: f32 in -> fp16 out ----------------------------------
__global__ void rope_h(const float* __restrict__ in, __half* __restrict__ out,
                       int nheads, float outscale) {
    int idx = blockIdx.x * blockDim.x + threadIdx.x;
    int total = PBS * nheads * 64;
    if (idx >= total) return;
    int i   = idx & 63;
    int t   = idx >> 6;
    int hh  = t % nheads;
    int row = t / nheads;
    int s   = row & (PS - 1);

    // 10000^(-i/64) = 2^(-i*log2(10000)/64)
    float inv = exp2f(-13.287712379549449f * (float)i * (1.f / 64.f));
    float ang = (float)s * inv;
    float sn, cs;
    sincosf(ang, &sn, &cs);

    size_t base = (size_t)row * (nheads * PHD) + hh * PHD;
    float x1 = in[base + i];
    float x2 = in[base + i + 64];
    out[base + i]      = __float2half_rn((x1 * cs - x2 * sn) * outscale);
    out[base + i + 64] = __float2half_rn((x2 * cs + x1 * sn) * outscale);
}

// ---------------- fp16 flash attention --------------------------------------
// 128 q-rows/CTA, 64 keys/iter, 8 warps (16 rows each). Double-buffered K/V.
// smem: Q 32KB | K0 16 | V0 16 | K1 16 | V1 16 | P 16 = 112KB
#define FM 128
#define FNC 64
#define OFF_K0 32768
#define OFF_V0 49152
#define OFF_K1 65536
#define OFF_V1 81920
#define OFF_P  98304
#define FLASH_SMEM 114688

__global__ __launch_bounds__(256, 1)
void flash_h(const __half* __restrict__ Q, const __half* __restrict__ K,
             const __half* __restrict__ V, __half* __restrict__ O) {
    extern __shared__ char sm[];
    const uint32_t sb = smem_u32(sm);
    const uint32_t kbuf[2] = {sb + OFF_K0, sb + OFF_K1};
    const uint32_t vbuf[2] = {sb + OFF_V0, sb + OFF_V1};
    const uint32_t pbuf = sb + OFF_P;

    const int tid  = threadIdx.x;
    const int lane = tid & 31;
    const int warp = tid >> 5;
    const int wm   = warp * 16;
    const int r    = lane >> 2;
    const int q4   = lane & 3;

    const int qtile = blockIdx.x;
    const int bh = blockIdx.y;
    const int b = bh >> 4, h = bh & 15;
    const int g = h >> 3;

    const __half* Qg = Q + ((size_t)(b * PS + qtile * FM)) * PD + h * PHD;
    const __half* Kg = K + ((size_t)(b * PS)) * KVW + g * PHD;
    const __half* Vg = V + ((size_t)(b * PS)) * KVW + g * PHD;

#define LOAD_KV(bi, k0) do {                                                    \
    _Pragma("unroll")                                                           \
    for (int i_ = 0; i_ < 4; i_++) {                                            \
        int e_ = tid + 256 * i_;                                                \
        int row_ = e_ >> 4, j_ = e_ & 15;                                       \
        cp16(kbuf[bi] + swz256(row_, j_), Kg + (size_t)((k0) + row_) * KVW + j_ * 8); \
        cp16(vbuf[bi] + swz256(row_, j_), Vg + (size_t)((k0) + row_) * KVW + j_ * 8); \
    } } while (0)

    // Q load + first K/V group
#pragma unroll
    for (int i_ = 0; i_ < 8; i_++) {
        int e_ = tid + 256 * i_;
        int row_ = e_ >> 4, j_ = e_ & 15;
        cp16(sb + swz256(row_, j_), Qg + (size_t)row_ * PD + j_ * 8);
    }
    LOAD_KV(0, 0);
    asm volatile("cp.async.commit_group;" ::: "memory");
    LOAD_KV(1, FNC);
    asm volatile("cp.async.commit_group;" ::: "memory");

    float m[2] = {-INFINITY, -INFINITY};
    float l[2] = {0.f, 0.f};
    float oacc[16][4];
#pragma unroll
    for (int nt = 0; nt < 16; nt++)
        oacc[nt][0] = oacc[nt][1] = oacc[nt][2] = oacc[nt][3] = 0.f;

    const int NIT = PS / FNC;   // 16
    for (int it = 0; it < NIT; ++it) {
        const int bi = it & 1;
        if (it < NIT - 1)
            asm volatile("cp.async.wait_group 1;" ::: "memory");
        else
            asm volatile("cp.async.wait_group 0;" ::: "memory");
        __syncthreads();

        // ---- S = Q @ K^T (warp: 16 x 64)
        float sacc[8][4];
#pragma unroll
        for (int nt = 0; nt < 8; nt++)
            sacc[nt][0] = sacc[nt][1] = sacc[nt][2] = sacc[nt][3] = 0.f;
#pragma unroll
        for (int ks = 0; ks < 8; ks++) {
            uint32_t af[4];
            {
                const int row = wm + (lane & 15);
                ldsm4(af, sb + swz256(row, ks * 2 + (lane >> 4)));
            }
#pragma unroll
            for (int knb = 0; knb < 4; knb++) {
                uint32_t bf[4];
                const int nrow = knb * 16 + (lane & 7) + ((lane >> 4) << 3);
                const int ch = ks * 2 + ((lane >> 3) & 1);
                ldsm4(bf, kbuf[bi] + swz256(nrow, ch));
                mma_f16(sacc[knb * 2],     af, bf);
                mma_f16(sacc[knb * 2 + 1], af, bf + 2);
            }
        }

        // ---- online softmax (scale already folded into Q)
        float mxA = -INFINITY, mxB = -INFINITY;
#pragma unroll
        for (int nt = 0; nt < 8; nt++) {
            mxA = fmaxf(mxA, fmaxf(sacc[nt][0], sacc[nt][1]));
            mxB = fmaxf(mxB, fmaxf(sacc[nt][2], sacc[nt][3]));
        }
        mxA = fmaxf(mxA, __shfl_xor_sync(0xffffffffu, mxA, 1));
        mxA = fmaxf(mxA, __shfl_xor_sync(0xffffffffu, mxA, 2));
        mxB = fmaxf(mxB, __shfl_xor_sync(0xffffffffu, mxB, 1));
        mxB = fmaxf(mxB, __shfl_xor_sync(0xffffffffu, mxB, 2));

        const float mnA = fmaxf(m[0], mxA);
        const float mnB = fmaxf(m[1], mxB);
        const float alA = __expf(m[0] - mnA);
        const float alB = __expf(m[1] - mnB);

        float rsA = 0.f, rsB = 0.f;
#pragma unroll
        for (int nt = 0; nt < 8; nt++) {
            float p0 = __expf(sacc[nt][0] - mnA);
            float p1 = __expf(sacc[nt][1] - mnA);
            float p2 = __expf(sacc[nt][2] - mnB);
            float p3 = __expf(sacc[nt][3] - mnB);
            rsA += p0 + p1; rsB += p2 + p3;
            *(__half2*)(sm + OFF_P + swz128(wm + r, nt) + q4 * 4) =
                __floats2half2_rn(p0, p1);
            *(__half2*)(sm + OFF_P + swz128(wm + r + 8, nt) + q4 * 4) =
                __floats2half2_rn(p2, p3);
        }
        rsA += __shfl_xor_sync(0xffffffffu, rsA, 1);
        rsA += __shfl_xor_sync(0xffffffffu, rsA, 2);
        rsB += __shfl_xor_sync(0xffffffffu, rsB, 1);
        rsB += __shfl_xor_sync(0xffffffffu, rsB, 2);

        l[0] = l[0] * alA + rsA;
        l[1] = l[1] * alB + rsB;
        m[0] = mnA; m[1] = mnB;
#pragma unroll
        for (int nt = 0; nt < 16; nt++) {
            oacc[nt][0] *= alA; oacc[nt][1] *= alA;
            oacc[nt][2] *= alB; oacc[nt][3] *= alB;
        }
        __syncwarp();   // P rows are warp-local

        // ---- O += P @ V (warp: 16 x 128)
#pragma unroll
        for (int ks = 0; ks < 4; ks++) {
            uint32_t af[4];
            {
                const int row = wm + (lane & 15);
                ldsm4(af, pbuf + swz128(row, ks * 2 + (lane >> 4)));
            }
#pragma unroll
            for (int nb = 0; nb < 8; nb++) {
                uint32_t bf[4];
                const int krow = ks * 16 + (lane & 15);
                const int ch = nb * 2 + (lane >> 4);
                ldsm4t(bf, vbuf[bi] + swz256(krow, ch));
                mma_f16(oacc[nb * 2],     af, bf);
                mma_f16(oacc[nb * 2 + 1], af, bf + 2);
            }
        }
        __syncthreads();   // everyone done with K/V[bi]

        if (it + 2 < NIT) {
            LOAD_KV(bi, (it + 2) * FNC);
            asm volatile("cp.async.commit_group;" ::: "memory");
        }
    }

    // epilogue: normalize, write fp16
    const float ivA = 1.f / l[0];
    const float ivB = 1.f / l[1];
    const int rowA = qtile * FM + wm + r;
    __half* opA = O + ((size_t)(b * PS + rowA)) * PD + h * PHD;
    __half* opB = opA + (size_t)8 * PD;
#pragma unroll
    for (int nt = 0; nt < 16; nt++) {
        const int c = nt * 8 + q4 * 2;
        *(__half2*)(opA + c) = __floats2half2_rn(oacc[nt][0] * ivA, oacc[nt][1] * ivA);
        *(__half2*)(opB + c) = __floats2half2_rn(oacc[nt][2] * ivB, oacc[nt][3] * ivB);
    }
}

// ---------------- launch ----------------------------------------------------
extern "C" void kernel_launch(void* const* d_in, const int* in_sizes, int n_in,
                              void* d_out, int out_size) {
    const float* x  = (const float*)d_in[0];
    const float* wq = (const float*)d_in[1];
    const float* bq = (const float*)d_in[2];
    const float* wk = (const float*)d_in[3];
    const float* bk = (const float*)d_in[4];
    const float* wv = (const float*)d_in[5];
    const float* bv = (const float*)d_in[6];
    const float* wo = (const float*)d_in[7];
    const float* bo = (const float*)d_in[8];
    float* out = (float*)d_out;

    float *pQ, *pK, *pBC;
    __half *pQH, *pKH, *pVH, *pXH, *pAOH, *pWCT, *pWOT;
    cudaGetSymbolAddress((void**)&pQ,   g_Q);
    cudaGetSymbolAddress((void**)&pK,   g_K);
    cudaGetSymbolAddress((void**)&pQH,  g_QH);
    cudaGetSymbolAddress((void**)&pKH,  g_KH);
    cudaGetSymbolAddress((void**)&pVH,  g_VH);
    cudaGetSymbolAddress((void**)&pXH,  g_XH);
    cudaGetSymbolAddress((void**)&pAOH, g_AOH);
    cudaGetSymbolAddress((void**)&pWCT, g_WCT);
    cudaGetSymbolAddress((void**)&pWOT, g_WOT);
    cudaGetSymbolAddress((void**)&pBC,  g_BC);

    cudaFuncSetAttribute(flash_h, cudaFuncAttributeMaxDynamicSharedMemorySize,
                         (int)FLASH_SMEM);
    cudaFuncSetAttribute(tgemm_h, cudaFuncAttributeMaxDynamicSharedMemorySize,
                         (int)HSMEM);
    cudaFuncSetAttribute(tgemm_qkv, cudaFuncAttributeMaxDynamicSharedMemorySize,
                         (int)HSMEM);

    // prep
    {
        int n8 = PBS * PD / 8;
        cvt_h_kernel<<<(n8 + 255) / 256, 256>>>(x, pXH, n8);
        transpose_h<<<dim3(PD / 32, PD / 32),  dim3(32, 8)>>>(wq, pWCT, PD, PD);
        transpose_h<<<dim3(KVW / 32, PD / 32), dim3(32, 8)>>>(wk, pWCT + (size_t)2048 * PD, PD, KVW);
        transpose_h<<<dim3(KVW / 32, PD / 32), dim3(32, 8)>>>(wv, pWCT + (size_t)2304 * PD, PD, KVW);
        transpose_h<<<dim3(PD / 32, PD / 32),  dim3(32, 8)>>>(wo, pWOT, PD, PD);
        concat_bias<<<10, 256>>>(bq, bk, bv, pBC);
    }

    // fused QKV projection
    tgemm_qkv<<<dim3(NQKV / 128, PBS / 128), 256, HSMEM>>>(pXH, pWCT, pBC, pQ, pK, pVH);

    // RoPE -> fp16 (Q gets hd^-1 = both hd^-0.5 factors)
    {
        int nq = PBS * PH * 64;
        rope_h<<<(nq + 255) / 256, 256>>>(pQ, pQH, PH, 0.0078125f);
        int nk = PBS * PG * 64;
        rope_h<<<(nk + 255) / 256, 256>>>(pK, pKH, PG, 1.0f);
    }

    // attention (fp16 tensor cores)
    flash_h<<<dim3(PS / FM, PB * PH), 256, FLASH_SMEM>>>(pQH, pKH, pVH, pAOH);

    // output projection
    tgemm_h<<<dim3(PD / 128, PBS / 128), 256, HSMEM>>>(pAOH, pWOT, bo, out, PD);
}